// round 11
// baseline (speedup 1.0000x reference)
#include <cuda_runtime.h>
#include <cstdint>

#define NPATH 11
#define XDIM 1152
#define YDIM 9
#define WPER 180224
#define NSAMP 1024
#define CGTOT 363
#define NCTA 444
#define NTASK 3072

// ================= Compile-time CG table (constexpr, fp64) =================

constexpr double cfac(int n) {
    double r = 1.0;
    for (int i = 2; i <= n; ++i) r *= (double)i;
    return r;
}

constexpr double csqrt(double x) {
    if (x <= 0.0) return 0.0;
    double g = x > 1.0 ? x : 1.0;
    for (int it = 0; it < 64; ++it) g = 0.5 * (g + x / g);
    return g;
}

constexpr double su2cg_c(int j1, int m1, int j2, int m2, int j3, int m3) {
    if (m1 + m2 != m3) return 0.0;
    int vmin = -j1 + j2 + m3;
    if (-j1 + m1 > vmin) vmin = -j1 + m1;
    if (vmin < 0) vmin = 0;
    int vmax = j2 + j3 + m1;
    if (j3 - j1 + j2 < vmax) vmax = j3 - j1 + j2;
    if (j3 + m3 < vmax) vmax = j3 + m3;
    double c = csqrt((2.0 * j3 + 1.0) * cfac(j3 + j1 - j2) * cfac(j3 - j1 + j2) * cfac(j1 + j2 - j3)
                     * cfac(j3 + m3) * cfac(j3 - m3)
                     / (cfac(j1 + j2 + j3 + 1) * cfac(j1 - m1) * cfac(j1 + m1)
                        * cfac(j2 - m2) * cfac(j2 + m2)));
    double s = 0.0;
    for (int v = vmin; v <= vmax; ++v) {
        double term = cfac(j2 + j3 + m1 - v) * cfac(j1 - m1 + v)
                      / (cfac(v) * cfac(j3 - j1 + j2 - v) * cfac(j3 + m3 - v) * cfac(v + j1 - j2 - m3));
        s += ((v + j2 + m2) & 1) ? -term : term;
    }
    return c * s;
}

struct QM { double re[25]; double im[25]; };

constexpr QM buildQ_c(int l) {
    QM q{};
    int d = 2 * l + 1;
    const double is2 = 0.70710678118654752440;
    for (int m = -l; m < 0; ++m) {
        q.re[(l + m) * d + (l - m)] = is2;
        q.im[(l + m) * d + (l + m)] = -is2;
    }
    q.re[l * d + l] = 1.0;
    for (int m = 1; m <= l; ++m) {
        double sgn = (m & 1) ? -1.0 : 1.0;
        q.re[(l + m) * d + (l + m)] = sgn * is2;
        q.im[(l + m) * d + (l - m)] = sgn * is2;
    }
    if (l == 1) {
        for (int e = 0; e < d * d; ++e) { double a = q.re[e], b = q.im[e]; q.re[e] = b; q.im[e] = -a; }
    } else if (l == 2) {
        for (int e = 0; e < d * d; ++e) { q.re[e] = -q.re[e]; q.im[e] = -q.im[e]; }
    }
    return q;
}

struct CGTable { float v[CGTOT]; };

constexpr CGTable makeCG() {
    CGTable T{};
    const int L1[NPATH]  = {0,0,0,1,1,1,1,2,2,2,2};
    const int L2[NPATH]  = {0,1,2,0,1,1,2,0,1,2,2};
    const int L3[NPATH]  = {0,1,2,1,0,2,1,2,1,0,2};
    const int CGO[NPATH] = {0,1,10,35,44,53,98,143,168,213,238};
    const double FAN[NPATH] = {384.,512.,512.,512.,384.,512.,512.,512.,512.,384.,512.};
    for (int p = 0; p < NPATH; ++p) {
        int l1 = L1[p], l2 = L2[p], l3 = L3[p];
        int d1 = 2*l1+1, d2 = 2*l2+1, d3 = 2*l3+1;
        QM Q1 = buildQ_c(l1), Q2 = buildQ_c(l2), Q3 = buildQ_c(l3);
        double C[125] = {};
        for (int i = 0; i < d1; ++i)
            for (int k = 0; k < d2; ++k)
                for (int nn = 0; nn < d3; ++nn)
                    C[(i*d2 + k)*d3 + nn] = su2cg_c(l1, i - l1, l2, k - l2, l3, nn - l3);
        double Cr[125] = {};
        double norm2 = 0.0;
        for (int jj = 0; jj < d1; ++jj)
            for (int ll = 0; ll < d2; ++ll)
                for (int mm = 0; mm < d3; ++mm) {
                    double sr = 0.0;
                    for (int i = 0; i < d1; ++i) {
                        double q1r = Q1.re[i*d1 + jj], q1i = Q1.im[i*d1 + jj];
                        for (int k = 0; k < d2; ++k) {
                            double q2r = Q2.re[k*d2 + ll], q2i = Q2.im[k*d2 + ll];
                            double ar = q1r*q2r - q1i*q2i;
                            double ai = q1r*q2i + q1i*q2r;
                            for (int nn = 0; nn < d3; ++nn) {
                                double c = C[(i*d2 + k)*d3 + nn];
                                sr += c * (ar * Q3.re[nn*d3 + mm] + ai * Q3.im[nn*d3 + mm]);
                            }
                        }
                    }
                    Cr[(jj*d2 + ll)*d3 + mm] = sr;
                    norm2 += sr * sr;
                }
        double scale = csqrt((double)(2*l3 + 1)) / (csqrt(norm2) * csqrt(FAN[p]));
        for (int e = 0; e < d1*d2*d3; ++e)
            T.v[CGO[p] + e] = (float)(Cr[e] * scale);
    }
    return T;
}

__constant__ CGTable c_cg = makeCG();

// pid lookup for runtime chunk addressing: pidTab[g][p]
__constant__ int c_pidTab[3][4] = { {0,4,9,0}, {1,3,6,8}, {2,5,7,10} };

// ---------------- Group tables ----------------

#define HDC static __host__ __device__ constexpr int

template<int G> struct GInfo;
template<> struct GInfo<0> {   // out l=0 (k=1): paths 0,4,9
    static constexpr int NP = 3, K3 = 1, OB = 0;
    HDC PID(int i) { return i==0 ? 0 : i==1 ? 4 : 9; }
    HDC D1 (int i) { return i==0 ? 1 : i==1 ? 3 : 5; }
    HDC D2 (int i) { return i==0 ? 1 : i==1 ? 3 : 5; }
    HDC XO (int i) { return i==0 ? 0 : i==1 ? 128 : 512; }
    HDC YO (int i) { return i==0 ? 0 : i==1 ? 1 : 4; }
    HDC CGO(int i) { return i==0 ? 0 : i==1 ? 44 : 213; }
};
template<> struct GInfo<1> {   // out l=1 (k=3): paths 1,3,6,8
    static constexpr int NP = 4, K3 = 3, OB = 128;
    HDC PID(int i) { return i==0 ? 1 : i==1 ? 3 : i==2 ? 6 : 8; }
    HDC D1 (int i) { return i==0 ? 1 : i==1 ? 3 : i==2 ? 3 : 5; }
    HDC D2 (int i) { return i==0 ? 3 : i==1 ? 1 : i==2 ? 5 : 3; }
    HDC XO (int i) { return i==0 ? 0 : i==1 ? 128 : i==2 ? 128 : 512; }
    HDC YO (int i) { return i==0 ? 1 : i==1 ? 0 : i==2 ? 4 : 1; }
    HDC CGO(int i) { return i==0 ? 1 : i==1 ? 35 : i==2 ? 98 : 168; }
};
template<> struct GInfo<2> {   // out l=2 (k=5): paths 2,5,7,10
    static constexpr int NP = 4, K3 = 5, OB = 512;
    HDC PID(int i) { return i==0 ? 2 : i==1 ? 5 : i==2 ? 7 : 10; }
    HDC D1 (int i) { return i==0 ? 1 : i==1 ? 3 : i==2 ? 5 : 5; }
    HDC D2 (int i) { return i==0 ? 5 : i==1 ? 3 : i==2 ? 1 : 5; }
    HDC XO (int i) { return i==0 ? 0 : i==1 ? 128 : i==2 ? 512 : 512; }
    HDC YO (int i) { return i==0 ? 4 : i==1 ? 1 : i==2 ? 0 : 4; }
    HDC CGO(int i) { return i==0 ? 10 : i==1 ? 53 : i==2 ? 143 : 238; }
};

// ---------------- SMEM layout (dynamic) ----------------
#define NSTAGE 4
#define STAGE_BYTES 16384
#define Z_OFF 65536           // 10240 B z / tree buffer
#define Y_OFF 75776           // 64 B
#define MB_OFF 75840          // 32 B (4 mbarriers)
#define CNT_OFF 75872         // 16 B (4 counters)
#define TG_OFF 75888          // 32 B (8 ints: task group)
#define TN_OFF 75920          // 32 B (8 ints: task sample)
#define CB_OFF 75952          // 48 B (9 ints: cumulative chunk base)
#define CO_OFF 76000          // 416 B (104 u32 chunk offsets, 16KB units)
#define SMEM_TOTAL 76416
#define MAXCHUNKS 104

// ---------------- PTX helpers ----------------

static __device__ __forceinline__ uint32_t smem_u32(const void* p) {
    return (uint32_t)__cvta_generic_to_shared(p);
}

static __device__ __forceinline__ void mbar_init(uint32_t a) {
    asm volatile("mbarrier.init.shared.b64 [%0], 1;" :: "r"(a) : "memory");
}

static __device__ __forceinline__ void mbar_expect(uint32_t a, uint32_t bytes) {
    asm volatile("mbarrier.arrive.expect_tx.shared.b64 _, [%0], %1;"
                 :: "r"(a), "r"(bytes) : "memory");
}

static __device__ __forceinline__ void bulk_cp(uint32_t dst, const void* src, uint32_t mbar) {
    asm volatile("cp.async.bulk.shared::cta.global.mbarrier::complete_tx::bytes [%0], [%1], %2, [%3];"
                 :: "r"(dst), "l"(src), "r"((uint32_t)STAGE_BYTES), "r"(mbar) : "memory");
}

static __device__ __forceinline__ void mbar_wait(uint32_t a, uint32_t parity) {
    asm volatile(
        "{\n\t.reg .pred P;\n"
        "LW_%=:\n\t"
        "mbarrier.try_wait.parity.acquire.cta.shared::cta.b64 P, [%0], %1, 0x989680;\n\t"
        "@P bra LD_%=;\n\t"
        "bra LW_%=;\n"
        "LD_%=:\n\t}"
        :: "r"(a), "r"(parity) : "memory");
}

static __device__ __forceinline__ void fadd2(unsigned long long& a, unsigned long long b) {
    asm("add.rn.f32x2 %0, %0, %1;" : "+l"(a) : "l"(b));
}

// ---------------- Phase-1 body ----------------

template<class GI>
__device__ __forceinline__ void phase1_path(GI, int pl,
                                            const float* __restrict__ x,
                                            const float* __restrict__ ysh,
                                            float* zsh, int n, int u) {
    constexpr int K3 = GI::K3;
    float zv[K3];
    #pragma unroll
    for (int k = 0; k < K3; k++) zv[k] = 0.f;
    const int d1 = GI::D1(pl), d2 = GI::D2(pl);
    const float* xb = x + (size_t)n * XDIM + GI::XO(pl) + u * d1;
    for (int i = 0; i < d1; i++) {
        float xv = xb[i];
        for (int j = 0; j < d2; j++) {
            float xy = xv * ysh[GI::YO(pl) + j];
            const float* cgr = c_cg.v + GI::CGO(pl) + (i * d2 + j) * K3;
            #pragma unroll
            for (int k = 0; k < K3; k++) zv[k] += cgr[k] * xy;
        }
    }
    int base = (pl * 128 + u) * K3;
    #pragma unroll
    for (int k = 0; k < K3; k++) zsh[base + k] = zv[k];
}

// ---------------- Per-task routine (one sample, one group) ----------------

template<int G>
__device__ __forceinline__ void run_task(const float* __restrict__ x,
                                         const float* __restrict__ y,
                                         const float* __restrict__ w,
                                         float* __restrict__ out,
                                         char* smem, int n, int cbase,
                                         int totalChunks, int t) {
    using GI = GInfo<G>;
    constexpr int NP = GI::NP, K3 = GI::K3;

    const int lane = t & 31, q = t >> 5;
    const uint32_t sb = smem_u32(smem);
    const uint32_t mb = sb + MB_OFF;
    float* zsh = (float*)(smem + Z_OFF);
    float* ysh = (float*)(smem + Y_OFF);
    int* cnt = (int*)(smem + CNT_OFF);
    const uint32_t* chunkOff = (const uint32_t*)(smem + CO_OFF);
    unsigned long long* tb = (unsigned long long*)(smem + Z_OFF);

    // ---- Phase 1 ----
    if (t < YDIM) ysh[t] = y[(size_t)n * YDIM + t];
    __syncthreads();   // ysh visible; previous task's tree reads of zsh done
    if (t < 128) {
        const int u = t;
        #pragma unroll
        for (int pl = 0; pl < NP; pl++)
            phase1_path(GI{}, pl, x, ysh, zsh, n, u);
    }
    __syncthreads();

    // ---- Phase 2: barrier-free chunk pipeline ----
    unsigned long long acc0[K3], acc1[K3];
    #pragma unroll
    for (int k = 0; k < K3; k++) { acc0[k] = 0ull; acc1[k] = 0ull; }

    #pragma unroll
    for (int p = 0; p < NP; p++) {
        #pragma unroll
        for (int r = 0; r < 4; r++) {
            const int cc = cbase + p * 4 + r;
            const int s = cc & (NSTAGE - 1);
            mbar_wait(mb + 8 * s, (cc >> 2) & 1);

            const char* wrow = smem + s * STAGE_BYTES + (q * 4) * 512 + lane * 16;
            const float* zp = zsh + (p * 128 + r * 32 + q * 4) * K3;
            #pragma unroll
            for (int ui = 0; ui < 4; ui++) {
                ulonglong2 wv = *reinterpret_cast<const ulonglong2*>(wrow + ui * 512);
                #pragma unroll
                for (int k = 0; k < K3; k++) {
                    float zk = zp[ui * K3 + k];
                    unsigned long long zz;
                    asm("mov.b64 %0, {%1, %1};" : "=l"(zz) : "f"(zk));
                    asm("fma.rn.f32x2 %0, %1, %2, %0;" : "+l"(acc0[k]) : "l"(wv.x), "l"(zz));
                    asm("fma.rn.f32x2 %0, %1, %2, %0;" : "+l"(acc1[k]) : "l"(wv.y), "l"(zz));
                }
            }
            if (lane == 0) {
                int old = atomicAdd(&cnt[s], 1);
                if ((old & 7) == 7) {
                    const int g2 = cc + NSTAGE;
                    if (g2 < totalChunks) {
                        mbar_expect(mb + 8 * s, STAGE_BYTES);
                        bulk_cp(sb + s * STAGE_BYTES,
                                (const char*)w + (size_t)chunkOff[g2] * STAGE_BYTES,
                                mb + 8 * s);
                    }
                }
            }
        }
    }
    __syncthreads();   // zsh reads done before tree overwrites it

    // ---- Phase 3: cross-warp tree reduction ----
    if (q >= 4) {
        int base = ((q - 4) * 32 + lane) * (2 * K3);
        #pragma unroll
        for (int k = 0; k < K3; k++) { tb[base + k] = acc0[k]; tb[base + K3 + k] = acc1[k]; }
    }
    __syncthreads();
    if (q < 4) {
        int base = (q * 32 + lane) * (2 * K3);
        #pragma unroll
        for (int k = 0; k < K3; k++) { fadd2(acc0[k], tb[base + k]); fadd2(acc1[k], tb[base + K3 + k]); }
    }
    __syncthreads();
    if (q >= 2 && q < 4) {
        int base = ((q - 2) * 32 + lane) * (2 * K3);
        #pragma unroll
        for (int k = 0; k < K3; k++) { tb[base + k] = acc0[k]; tb[base + K3 + k] = acc1[k]; }
    }
    __syncthreads();
    if (q < 2) {
        int base = (q * 32 + lane) * (2 * K3);
        #pragma unroll
        for (int k = 0; k < K3; k++) { fadd2(acc0[k], tb[base + k]); fadd2(acc1[k], tb[base + K3 + k]); }
    }
    __syncthreads();
    if (q == 1) {
        int base = lane * (2 * K3);
        #pragma unroll
        for (int k = 0; k < K3; k++) { tb[base + k] = acc0[k]; tb[base + K3 + k] = acc1[k]; }
    }
    __syncthreads();
    if (q == 0) {
        int base = lane * (2 * K3);
        float* outn = out + (size_t)n * XDIM + GI::OB + lane * (4 * K3);
        float res[4 * K3];
        #pragma unroll
        for (int k = 0; k < K3; k++) {
            fadd2(acc0[k], tb[base + k]);
            fadd2(acc1[k], tb[base + K3 + k]);
            float lo, hi;
            asm("mov.b64 {%0,%1}, %2;" : "=f"(lo), "=f"(hi) : "l"(acc0[k]));
            res[0 * K3 + k] = lo;
            res[1 * K3 + k] = hi;
            asm("mov.b64 {%0,%1}, %2;" : "=f"(lo), "=f"(hi) : "l"(acc1[k]));
            res[2 * K3 + k] = lo;
            res[3 * K3 + k] = hi;
        }
        #pragma unroll
        for (int v = 0; v < K3; v++)
            reinterpret_cast<float4*>(outn)[v] =
                reinterpret_cast<const float4*>(res)[v];
    }
}

// ---------------- Kernel: byte-balanced persistent task loop ----------------

extern __shared__ char dsmem[];

__global__ void __launch_bounds__(256, 3)
tp_kernel(const float* __restrict__ x,
          const float* __restrict__ y,
          const float* __restrict__ w,
          float* __restrict__ out) {
    char* smem = dsmem;
    const int bx = blockIdx.x, t = threadIdx.x;
    const uint32_t sb = smem_u32(smem);
    const uint32_t mb = sb + MB_OFF;
    int* cnt = (int*)(smem + CNT_OFF);
    int* taskG = (int*)(smem + TG_OFF);
    int* taskN = (int*)(smem + TN_OFF);
    int* cbArr = (int*)(smem + CB_OFF);
    uint32_t* chunkOff = (uint32_t*)(smem + CO_OFF);

    // ---- Build task list: tasks ordered [g1 x1024 | g2 x1024 | g0 x1024],
    //      dealt round-robin with stride NCTA for byte balance. ----
    if (t == 0) {
        int cb = 0, k = 0;
        #pragma unroll
        for (int kk = 0; kk < 7; kk++) {
            int tau = bx + NCTA * kk;
            if (tau < NTASK) {
                int g, n;
                if (tau < 1024)      { g = 1; n = tau; }
                else if (tau < 2048) { g = 2; n = tau - 1024; }
                else                 { g = 0; n = tau - 2048; }
                taskG[k] = g; taskN[k] = n; cbArr[k] = cb;
                cb += (g == 0) ? 12 : 16;
                k++;
            }
        }
        cbArr[k] = cb;
        taskG[7] = k;   // store ntasks in slot 7
        #pragma unroll
        for (int s = 0; s < NSTAGE; s++) { mbar_init(mb + 8 * s); cnt[s] = 0; }
    }
    __syncthreads();

    const int ntasks = taskG[7];
    const int totalChunks = cbArr[ntasks];

    // ---- Fill chunk source-offset table (16KB units) ----
    for (int idx = t; idx < totalChunks; idx += 256) {
        int k = 0;
        while (cbArr[k + 1] <= idx) k++;
        int c = idx - cbArr[k];
        int g = taskG[k], n = taskN[k];
        int pid = c_pidTab[g][c >> 2];
        chunkOff[idx] = (uint32_t)(n * 44 + pid * 4 + (c & 3));
    }
    __syncthreads();

    // ---- Initial prefetch ----
    if (t == 0) {
        #pragma unroll
        for (int s = 0; s < NSTAGE; s++) {
            mbar_expect(mb + 8 * s, STAGE_BYTES);
            bulk_cp(sb + s * STAGE_BYTES,
                    (const char*)w + (size_t)chunkOff[s] * STAGE_BYTES, mb + 8 * s);
        }
    }

    // ---- Task loop ----
    for (int k = 0; k < ntasks; k++) {
        const int g = taskG[k], n = taskN[k], cb = cbArr[k];
        if (g == 1)      run_task<1>(x, y, w, out, smem, n, cb, totalChunks, t);
        else if (g == 2) run_task<2>(x, y, w, out, smem, n, cb, totalChunks, t);
        else             run_task<0>(x, y, w, out, smem, n, cb, totalChunks, t);
    }
}

extern "C" void kernel_launch(void* const* d_in, const int* in_sizes, int n_in,
                              void* d_out, int out_size) {
    const float* x = nullptr;
    const float* y = nullptr;
    const float* w = nullptr;
    for (int i = 0; i < n_in; i++) {
        long sz = in_sizes[i];
        if      (sz == (long)NSAMP * XDIM) x = (const float*)d_in[i];
        else if (sz == (long)NSAMP * YDIM) y = (const float*)d_in[i];
        else if (sz == (long)NSAMP * WPER) w = (const float*)d_in[i];
    }
    if (!x) x = (const float*)d_in[0];
    if (!y) y = (const float*)d_in[1];
    if (!w) w = (const float*)d_in[2];

    cudaFuncSetAttribute(tp_kernel, cudaFuncAttributeMaxDynamicSharedMemorySize, SMEM_TOTAL);
    tp_kernel<<<NCTA, 256, SMEM_TOTAL>>>(x, y, w, (float*)d_out);
}

// round 12
// speedup vs baseline: 1.0169x; 1.0169x over previous
#include <cuda_runtime.h>
#include <cstdint>

#define NPATH 11
#define XDIM 1152
#define YDIM 9
#define WPER 180224
#define NSAMP 1024
#define CGTOT 363
#define NSM 148

// ================= Compile-time CG table (constexpr, fp64) =================

constexpr double cfac(int n) {
    double r = 1.0;
    for (int i = 2; i <= n; ++i) r *= (double)i;
    return r;
}

constexpr double csqrt(double x) {
    if (x <= 0.0) return 0.0;
    double g = x > 1.0 ? x : 1.0;
    for (int it = 0; it < 64; ++it) g = 0.5 * (g + x / g);
    return g;
}

constexpr double su2cg_c(int j1, int m1, int j2, int m2, int j3, int m3) {
    if (m1 + m2 != m3) return 0.0;
    int vmin = -j1 + j2 + m3;
    if (-j1 + m1 > vmin) vmin = -j1 + m1;
    if (vmin < 0) vmin = 0;
    int vmax = j2 + j3 + m1;
    if (j3 - j1 + j2 < vmax) vmax = j3 - j1 + j2;
    if (j3 + m3 < vmax) vmax = j3 + m3;
    double c = csqrt((2.0 * j3 + 1.0) * cfac(j3 + j1 - j2) * cfac(j3 - j1 + j2) * cfac(j1 + j2 - j3)
                     * cfac(j3 + m3) * cfac(j3 - m3)
                     / (cfac(j1 + j2 + j3 + 1) * cfac(j1 - m1) * cfac(j1 + m1)
                        * cfac(j2 - m2) * cfac(j2 + m2)));
    double s = 0.0;
    for (int v = vmin; v <= vmax; ++v) {
        double term = cfac(j2 + j3 + m1 - v) * cfac(j1 - m1 + v)
                      / (cfac(v) * cfac(j3 - j1 + j2 - v) * cfac(j3 + m3 - v) * cfac(v + j1 - j2 - m3));
        s += ((v + j2 + m2) & 1) ? -term : term;
    }
    return c * s;
}

struct QM { double re[25]; double im[25]; };

constexpr QM buildQ_c(int l) {
    QM q{};
    int d = 2 * l + 1;
    const double is2 = 0.70710678118654752440;
    for (int m = -l; m < 0; ++m) {
        q.re[(l + m) * d + (l - m)] = is2;
        q.im[(l + m) * d + (l + m)] = -is2;
    }
    q.re[l * d + l] = 1.0;
    for (int m = 1; m <= l; ++m) {
        double sgn = (m & 1) ? -1.0 : 1.0;
        q.re[(l + m) * d + (l + m)] = sgn * is2;
        q.im[(l + m) * d + (l - m)] = sgn * is2;
    }
    if (l == 1) {
        for (int e = 0; e < d * d; ++e) { double a = q.re[e], b = q.im[e]; q.re[e] = b; q.im[e] = -a; }
    } else if (l == 2) {
        for (int e = 0; e < d * d; ++e) { q.re[e] = -q.re[e]; q.im[e] = -q.im[e]; }
    }
    return q;
}

struct CGTable { float v[CGTOT]; };

constexpr CGTable makeCG() {
    CGTable T{};
    const int L1[NPATH]  = {0,0,0,1,1,1,1,2,2,2,2};
    const int L2[NPATH]  = {0,1,2,0,1,1,2,0,1,2,2};
    const int L3[NPATH]  = {0,1,2,1,0,2,1,2,1,0,2};
    const int CGO[NPATH] = {0,1,10,35,44,53,98,143,168,213,238};
    const double FAN[NPATH] = {384.,512.,512.,512.,384.,512.,512.,512.,512.,384.,512.};
    for (int p = 0; p < NPATH; ++p) {
        int l1 = L1[p], l2 = L2[p], l3 = L3[p];
        int d1 = 2*l1+1, d2 = 2*l2+1, d3 = 2*l3+1;
        QM Q1 = buildQ_c(l1), Q2 = buildQ_c(l2), Q3 = buildQ_c(l3);
        double C[125] = {};
        for (int i = 0; i < d1; ++i)
            for (int k = 0; k < d2; ++k)
                for (int nn = 0; nn < d3; ++nn)
                    C[(i*d2 + k)*d3 + nn] = su2cg_c(l1, i - l1, l2, k - l2, l3, nn - l3);
        double Cr[125] = {};
        double norm2 = 0.0;
        for (int jj = 0; jj < d1; ++jj)
            for (int ll = 0; ll < d2; ++ll)
                for (int mm = 0; mm < d3; ++mm) {
                    double sr = 0.0;
                    for (int i = 0; i < d1; ++i) {
                        double q1r = Q1.re[i*d1 + jj], q1i = Q1.im[i*d1 + jj];
                        for (int k = 0; k < d2; ++k) {
                            double q2r = Q2.re[k*d2 + ll], q2i = Q2.im[k*d2 + ll];
                            double ar = q1r*q2r - q1i*q2i;
                            double ai = q1r*q2i + q1i*q2r;
                            for (int nn = 0; nn < d3; ++nn) {
                                double c = C[(i*d2 + k)*d3 + nn];
                                sr += c * (ar * Q3.re[nn*d3 + mm] + ai * Q3.im[nn*d3 + mm]);
                            }
                        }
                    }
                    Cr[(jj*d2 + ll)*d3 + mm] = sr;
                    norm2 += sr * sr;
                }
        double scale = csqrt((double)(2*l3 + 1)) / (csqrt(norm2) * csqrt(FAN[p]));
        for (int e = 0; e < d1*d2*d3; ++e)
            T.v[CGO[p] + e] = (float)(Cr[e] * scale);
    }
    return T;
}

__constant__ CGTable c_cg = makeCG();

// ---------------- Group tables ----------------

#define HDC static __host__ __device__ constexpr int

template<int G> struct GInfo;
template<> struct GInfo<0> {   // out l=0 (k=1): paths 0,4,9
    static constexpr int NP = 3, K3 = 1, OB = 0;
    HDC PID(int i) { return i==0 ? 0 : i==1 ? 4 : 9; }
    HDC D1 (int i) { return i==0 ? 1 : i==1 ? 3 : 5; }
    HDC D2 (int i) { return i==0 ? 1 : i==1 ? 3 : 5; }
    HDC XO (int i) { return i==0 ? 0 : i==1 ? 128 : 512; }
    HDC YO (int i) { return i==0 ? 0 : i==1 ? 1 : 4; }
    HDC CGO(int i) { return i==0 ? 0 : i==1 ? 44 : 213; }
};
template<> struct GInfo<1> {   // out l=1 (k=3): paths 1,3,6,8
    static constexpr int NP = 4, K3 = 3, OB = 128;
    HDC PID(int i) { return i==0 ? 1 : i==1 ? 3 : i==2 ? 6 : 8; }
    HDC D1 (int i) { return i==0 ? 1 : i==1 ? 3 : i==2 ? 3 : 5; }
    HDC D2 (int i) { return i==0 ? 3 : i==1 ? 1 : i==2 ? 5 : 3; }
    HDC XO (int i) { return i==0 ? 0 : i==1 ? 128 : i==2 ? 128 : 512; }
    HDC YO (int i) { return i==0 ? 1 : i==1 ? 0 : i==2 ? 4 : 1; }
    HDC CGO(int i) { return i==0 ? 1 : i==1 ? 35 : i==2 ? 98 : 168; }
};
template<> struct GInfo<2> {   // out l=2 (k=5): paths 2,5,7,10
    static constexpr int NP = 4, K3 = 5, OB = 512;
    HDC PID(int i) { return i==0 ? 2 : i==1 ? 5 : i==2 ? 7 : 10; }
    HDC D1 (int i) { return i==0 ? 1 : i==1 ? 3 : i==2 ? 5 : 5; }
    HDC D2 (int i) { return i==0 ? 5 : i==1 ? 3 : i==2 ? 1 : 5; }
    HDC XO (int i) { return i==0 ? 0 : i==1 ? 128 : i==2 ? 512 : 512; }
    HDC YO (int i) { return i==0 ? 4 : i==1 ? 1 : i==2 ? 0 : 4; }
    HDC CGO(int i) { return i==0 ? 10 : i==1 ? 53 : i==2 ? 143 : 238; }
};

// ---------------- SMEM layout (dynamic) ----------------
// [0, 65536)      : 8 stages x 8KB weight ring (always live, persistent)
// [65536, 75776)  : z buffer (phase 1/2) — reused as phase-3 tree buffer
// [75776, 75840)  : ysh
// [75840, 75904)  : 8 mbarriers
// [75904, 75936)  : 8 per-stage monotonic consume counters
#define NSTAGE 8
#define STAGE_BYTES 8192
#define Z_OFF 65536
#define Y_OFF 75776
#define MB_OFF 75840
#define CNT_OFF 75904
#define SMEM_TOTAL 75936

// ---------------- PTX helpers ----------------

static __device__ __forceinline__ uint32_t smem_u32(const void* p) {
    return (uint32_t)__cvta_generic_to_shared(p);
}

static __device__ __forceinline__ void mbar_init(uint32_t a) {
    asm volatile("mbarrier.init.shared.b64 [%0], 1;" :: "r"(a) : "memory");
}

static __device__ __forceinline__ void mbar_expect(uint32_t a, uint32_t bytes) {
    asm volatile("mbarrier.arrive.expect_tx.shared.b64 _, [%0], %1;"
                 :: "r"(a), "r"(bytes) : "memory");
}

static __device__ __forceinline__ void bulk_cp(uint32_t dst, const void* src, uint32_t mbar) {
    asm volatile("cp.async.bulk.shared::cta.global.mbarrier::complete_tx::bytes [%0], [%1], %2, [%3];"
                 :: "r"(dst), "l"(src), "r"((uint32_t)STAGE_BYTES), "r"(mbar) : "memory");
}

static __device__ __forceinline__ void mbar_wait(uint32_t a, uint32_t parity) {
    asm volatile(
        "{\n\t.reg .pred P;\n"
        "LW_%=:\n\t"
        "mbarrier.try_wait.parity.acquire.cta.shared::cta.b64 P, [%0], %1, 0x989680;\n\t"
        "@P bra LD_%=;\n\t"
        "bra LW_%=;\n"
        "LD_%=:\n\t}"
        :: "r"(a), "r"(parity) : "memory");
}

static __device__ __forceinline__ void fadd2(unsigned long long& a, unsigned long long b) {
    asm("add.rn.f32x2 %0, %0, %1;" : "+l"(a) : "l"(b));
}

// ---------------- Phase-1 body ----------------

template<class GI>
__device__ __forceinline__ void phase1_path(GI, int pl,
                                            const float* __restrict__ x,
                                            const float* __restrict__ ysh,
                                            float* zsh, int n, int u) {
    constexpr int K3 = GI::K3;
    float zv[K3];
    #pragma unroll
    for (int k = 0; k < K3; k++) zv[k] = 0.f;
    const int d1 = GI::D1(pl), d2 = GI::D2(pl);
    const float* xb = x + (size_t)n * XDIM + GI::XO(pl) + u * d1;
    for (int i = 0; i < d1; i++) {
        float xv = xb[i];
        for (int j = 0; j < d2; j++) {
            float xy = xv * ysh[GI::YO(pl) + j];
            const float* cgr = c_cg.v + GI::CGO(pl) + (i * d2 + j) * K3;
            #pragma unroll
            for (int k = 0; k < K3; k++) zv[k] += cgr[k] * xy;
        }
    }
    int base = (pl * 128 + u) * K3;
    #pragma unroll
    for (int k = 0; k < K3; k++) zsh[base + k] = zv[k];
}

// ---------------- Persistent group routine ----------------

template<int G>
__device__ __forceinline__ void run_group(const float* __restrict__ x,
                                          const float* __restrict__ y,
                                          const float* __restrict__ w,
                                          float* __restrict__ out,
                                          char* smem, int bx, int t) {
    using GI = GInfo<G>;
    constexpr int NP = GI::NP, K3 = GI::K3;
    constexpr int NCHUNK = NP * 8;              // 8KB chunks (16 u-rows each)

    const int lane = t & 31, q = t >> 5;
    const uint32_t sb = smem_u32(smem);
    const uint32_t mb = sb + MB_OFF;
    float* zsh = (float*)(smem + Z_OFF);
    float* ysh = (float*)(smem + Y_OFF);
    int* cnt = (int*)(smem + CNT_OFF);
    unsigned long long* tb = (unsigned long long*)(smem + Z_OFF); // tree buffer

    const int snum = (NSAMP - bx + NSM - 1) / NSM;   // samples for this CTA
    const int totalChunks = snum * NCHUNK;

    if (t == 0) {
        #pragma unroll
        for (int s = 0; s < NSTAGE; s++) { mbar_init(mb + 8 * s); cnt[s] = 0; }
    }
    __syncthreads();

    // global chunk g -> source address
    auto chunk_src = [&](int g) -> const char* {
        const int j2 = g / NCHUNK;
        const int c2 = g - j2 * NCHUNK;
        const int n2 = bx + NSM * j2;
        return (const char*)w + (size_t)n2 * (WPER * 4)
               + GI::PID(c2 >> 3) * 65536 + (c2 & 7) * STAGE_BYTES;
    };

    // initial prefetch
    if (t == 0) {
        #pragma unroll
        for (int s = 0; s < NSTAGE; s++) {
            mbar_expect(mb + 8 * s, STAGE_BYTES);
            bulk_cp(sb + s * STAGE_BYTES, chunk_src(s), mb + 8 * s);
        }
    }

    for (int j = 0; j < snum; j++) {
        const int n = bx + NSM * j;

        // ---- Phase 1 (TMA streams in background) ----
        if (t < YDIM) ysh[t] = y[(size_t)n * YDIM + t];
        __syncthreads();   // ysh visible; previous sample's tree reads of zsh done
        if (t < 128) {
            const int u = t;
            #pragma unroll
            for (int pl = 0; pl < NP; pl++)
                phase1_path(GI{}, pl, x, ysh, zsh, n, u);
        }
        __syncthreads();

        // ---- Phase 2: barrier-free chunk pipeline ("last consumer refills") ----
        unsigned long long acc0[K3], acc1[K3];
        #pragma unroll
        for (int k = 0; k < K3; k++) { acc0[k] = 0ull; acc1[k] = 0ull; }

        #pragma unroll
        for (int p = 0; p < NP; p++) {
            #pragma unroll
            for (int r = 0; r < 8; r++) {
                const int cc = j * NCHUNK + p * 8 + r;
                const int s = cc & (NSTAGE - 1);
                mbar_wait(mb + 8 * s, (cc >> 3) & 1);

                // warp q consumes rows q*2 .. q*2+1 of this 16-row chunk
                const char* wrow = smem + s * STAGE_BYTES + (q * 2) * 512 + lane * 16;
                const float* zp = zsh + (p * 128 + r * 16 + q * 2) * K3;
                #pragma unroll
                for (int ui = 0; ui < 2; ui++) {
                    ulonglong2 wv = *reinterpret_cast<const ulonglong2*>(wrow + ui * 512);
                    #pragma unroll
                    for (int k = 0; k < K3; k++) {
                        float zk = zp[ui * K3 + k];
                        unsigned long long zz;
                        asm("mov.b64 %0, {%1, %1};" : "=l"(zz) : "f"(zk));
                        asm("fma.rn.f32x2 %0, %1, %2, %0;" : "+l"(acc0[k]) : "l"(wv.x), "l"(zz));
                        asm("fma.rn.f32x2 %0, %1, %2, %0;" : "+l"(acc1[k]) : "l"(wv.y), "l"(zz));
                    }
                }
                // last consumer of this stage issues the refill immediately
                if (lane == 0) {
                    int old = atomicAdd(&cnt[s], 1);
                    if ((old & 7) == 7) {
                        const int g = cc + NSTAGE;
                        if (g < totalChunks) {
                            mbar_expect(mb + 8 * s, STAGE_BYTES);
                            bulk_cp(sb + s * STAGE_BYTES, chunk_src(g), mb + 8 * s);
                        }
                    }
                }
            }
        }
        __syncthreads();   // all warps done with zsh reads before tree overwrites it

        // ---- Phase 3: cross-warp tree reduction through z buffer ----
        if (q >= 4) {
            int base = ((q - 4) * 32 + lane) * (2 * K3);
            #pragma unroll
            for (int k = 0; k < K3; k++) { tb[base + k] = acc0[k]; tb[base + K3 + k] = acc1[k]; }
        }
        __syncthreads();
        if (q < 4) {
            int base = (q * 32 + lane) * (2 * K3);
            #pragma unroll
            for (int k = 0; k < K3; k++) { fadd2(acc0[k], tb[base + k]); fadd2(acc1[k], tb[base + K3 + k]); }
        }
        __syncthreads();
        if (q >= 2 && q < 4) {
            int base = ((q - 2) * 32 + lane) * (2 * K3);
            #pragma unroll
            for (int k = 0; k < K3; k++) { tb[base + k] = acc0[k]; tb[base + K3 + k] = acc1[k]; }
        }
        __syncthreads();
        if (q < 2) {
            int base = (q * 32 + lane) * (2 * K3);
            #pragma unroll
            for (int k = 0; k < K3; k++) { fadd2(acc0[k], tb[base + k]); fadd2(acc1[k], tb[base + K3 + k]); }
        }
        __syncthreads();
        if (q == 1) {
            int base = lane * (2 * K3);
            #pragma unroll
            for (int k = 0; k < K3; k++) { tb[base + k] = acc0[k]; tb[base + K3 + k] = acc1[k]; }
        }
        __syncthreads();
        if (q == 0) {
            int base = lane * (2 * K3);
            float* outn = out + (size_t)n * XDIM + GI::OB + lane * (4 * K3);
            float res[4 * K3];
            #pragma unroll
            for (int k = 0; k < K3; k++) {
                fadd2(acc0[k], tb[base + k]);
                fadd2(acc1[k], tb[base + K3 + k]);
                float lo, hi;
                asm("mov.b64 {%0,%1}, %2;" : "=f"(lo), "=f"(hi) : "l"(acc0[k]));
                res[0 * K3 + k] = lo;
                res[1 * K3 + k] = hi;
                asm("mov.b64 {%0,%1}, %2;" : "=f"(lo), "=f"(hi) : "l"(acc1[k]));
                res[2 * K3 + k] = lo;
                res[3 * K3 + k] = hi;
            }
            #pragma unroll
            for (int v = 0; v < K3; v++)
                reinterpret_cast<float4*>(outn)[v] =
                    reinterpret_cast<const float4*>(res)[v];
        }
        // loop-top __syncthreads protects zsh/ysh reuse
    }
}

extern __shared__ char dsmem[];

__global__ void __launch_bounds__(256, 3)
tp_kernel(const float* __restrict__ x,
          const float* __restrict__ y,
          const float* __restrict__ w,
          float* __restrict__ out) {
    const int bx = blockIdx.x, g = blockIdx.y, t = threadIdx.x;
    if (g == 0)      run_group<0>(x, y, w, out, dsmem, bx, t);
    else if (g == 1) run_group<1>(x, y, w, out, dsmem, bx, t);
    else             run_group<2>(x, y, w, out, dsmem, bx, t);
}

extern "C" void kernel_launch(void* const* d_in, const int* in_sizes, int n_in,
                              void* d_out, int out_size) {
    const float* x = nullptr;
    const float* y = nullptr;
    const float* w = nullptr;
    for (int i = 0; i < n_in; i++) {
        long sz = in_sizes[i];
        if      (sz == (long)NSAMP * XDIM) x = (const float*)d_in[i];
        else if (sz == (long)NSAMP * YDIM) y = (const float*)d_in[i];
        else if (sz == (long)NSAMP * WPER) w = (const float*)d_in[i];
    }
    if (!x) x = (const float*)d_in[0];
    if (!y) y = (const float*)d_in[1];
    if (!w) w = (const float*)d_in[2];

    cudaFuncSetAttribute(tp_kernel, cudaFuncAttributeMaxDynamicSharedMemorySize, SMEM_TOTAL);
    tp_kernel<<<dim3(NSM, 3), 256, SMEM_TOTAL>>>(x, y, w, (float*)d_out);
}

// round 13
// speedup vs baseline: 1.0564x; 1.0389x over previous
#include <cuda_runtime.h>
#include <cstdint>

#define NPATH 11
#define XDIM 1152
#define YDIM 9
#define WPER 180224
#define NSAMP 1024
#define CGTOT 363
#define NSM 148

// ================= Compile-time CG table (constexpr, fp64) =================

constexpr double cfac(int n) {
    double r = 1.0;
    for (int i = 2; i <= n; ++i) r *= (double)i;
    return r;
}

constexpr double csqrt(double x) {
    if (x <= 0.0) return 0.0;
    double g = x > 1.0 ? x : 1.0;
    for (int it = 0; it < 64; ++it) g = 0.5 * (g + x / g);
    return g;
}

constexpr double su2cg_c(int j1, int m1, int j2, int m2, int j3, int m3) {
    if (m1 + m2 != m3) return 0.0;
    int vmin = -j1 + j2 + m3;
    if (-j1 + m1 > vmin) vmin = -j1 + m1;
    if (vmin < 0) vmin = 0;
    int vmax = j2 + j3 + m1;
    if (j3 - j1 + j2 < vmax) vmax = j3 - j1 + j2;
    if (j3 + m3 < vmax) vmax = j3 + m3;
    double c = csqrt((2.0 * j3 + 1.0) * cfac(j3 + j1 - j2) * cfac(j3 - j1 + j2) * cfac(j1 + j2 - j3)
                     * cfac(j3 + m3) * cfac(j3 - m3)
                     / (cfac(j1 + j2 + j3 + 1) * cfac(j1 - m1) * cfac(j1 + m1)
                        * cfac(j2 - m2) * cfac(j2 + m2)));
    double s = 0.0;
    for (int v = vmin; v <= vmax; ++v) {
        double term = cfac(j2 + j3 + m1 - v) * cfac(j1 - m1 + v)
                      / (cfac(v) * cfac(j3 - j1 + j2 - v) * cfac(j3 + m3 - v) * cfac(v + j1 - j2 - m3));
        s += ((v + j2 + m2) & 1) ? -term : term;
    }
    return c * s;
}

struct QM { double re[25]; double im[25]; };

constexpr QM buildQ_c(int l) {
    QM q{};
    int d = 2 * l + 1;
    const double is2 = 0.70710678118654752440;
    for (int m = -l; m < 0; ++m) {
        q.re[(l + m) * d + (l - m)] = is2;
        q.im[(l + m) * d + (l + m)] = -is2;
    }
    q.re[l * d + l] = 1.0;
    for (int m = 1; m <= l; ++m) {
        double sgn = (m & 1) ? -1.0 : 1.0;
        q.re[(l + m) * d + (l + m)] = sgn * is2;
        q.im[(l + m) * d + (l - m)] = sgn * is2;
    }
    if (l == 1) {
        for (int e = 0; e < d * d; ++e) { double a = q.re[e], b = q.im[e]; q.re[e] = b; q.im[e] = -a; }
    } else if (l == 2) {
        for (int e = 0; e < d * d; ++e) { q.re[e] = -q.re[e]; q.im[e] = -q.im[e]; }
    }
    return q;
}

struct CGTable { float v[CGTOT]; };

constexpr CGTable makeCG() {
    CGTable T{};
    const int L1[NPATH]  = {0,0,0,1,1,1,1,2,2,2,2};
    const int L2[NPATH]  = {0,1,2,0,1,1,2,0,1,2,2};
    const int L3[NPATH]  = {0,1,2,1,0,2,1,2,1,0,2};
    const int CGO[NPATH] = {0,1,10,35,44,53,98,143,168,213,238};
    const double FAN[NPATH] = {384.,512.,512.,512.,384.,512.,512.,512.,512.,384.,512.};
    for (int p = 0; p < NPATH; ++p) {
        int l1 = L1[p], l2 = L2[p], l3 = L3[p];
        int d1 = 2*l1+1, d2 = 2*l2+1, d3 = 2*l3+1;
        QM Q1 = buildQ_c(l1), Q2 = buildQ_c(l2), Q3 = buildQ_c(l3);
        double C[125] = {};
        for (int i = 0; i < d1; ++i)
            for (int k = 0; k < d2; ++k)
                for (int nn = 0; nn < d3; ++nn)
                    C[(i*d2 + k)*d3 + nn] = su2cg_c(l1, i - l1, l2, k - l2, l3, nn - l3);
        double Cr[125] = {};
        double norm2 = 0.0;
        for (int jj = 0; jj < d1; ++jj)
            for (int ll = 0; ll < d2; ++ll)
                for (int mm = 0; mm < d3; ++mm) {
                    double sr = 0.0;
                    for (int i = 0; i < d1; ++i) {
                        double q1r = Q1.re[i*d1 + jj], q1i = Q1.im[i*d1 + jj];
                        for (int k = 0; k < d2; ++k) {
                            double q2r = Q2.re[k*d2 + ll], q2i = Q2.im[k*d2 + ll];
                            double ar = q1r*q2r - q1i*q2i;
                            double ai = q1r*q2i + q1i*q2r;
                            for (int nn = 0; nn < d3; ++nn) {
                                double c = C[(i*d2 + k)*d3 + nn];
                                sr += c * (ar * Q3.re[nn*d3 + mm] + ai * Q3.im[nn*d3 + mm]);
                            }
                        }
                    }
                    Cr[(jj*d2 + ll)*d3 + mm] = sr;
                    norm2 += sr * sr;
                }
        double scale = csqrt((double)(2*l3 + 1)) / (csqrt(norm2) * csqrt(FAN[p]));
        for (int e = 0; e < d1*d2*d3; ++e)
            T.v[CGO[p] + e] = (float)(Cr[e] * scale);
    }
    return T;
}

__constant__ CGTable c_cg = makeCG();

// ---------------- Group tables ----------------

#define HDC static __host__ __device__ constexpr int

template<int G> struct GInfo;
template<> struct GInfo<0> {   // out l=0 (k=1): paths 0,4,9
    static constexpr int NP = 3, K3 = 1, OB = 0;
    HDC PID(int i) { return i==0 ? 0 : i==1 ? 4 : 9; }
    HDC D1 (int i) { return i==0 ? 1 : i==1 ? 3 : 5; }
    HDC D2 (int i) { return i==0 ? 1 : i==1 ? 3 : 5; }
    HDC XO (int i) { return i==0 ? 0 : i==1 ? 128 : 512; }
    HDC YO (int i) { return i==0 ? 0 : i==1 ? 1 : 4; }
    HDC CGO(int i) { return i==0 ? 0 : i==1 ? 44 : 213; }
};
template<> struct GInfo<1> {   // out l=1 (k=3): paths 1,3,6,8
    static constexpr int NP = 4, K3 = 3, OB = 128;
    HDC PID(int i) { return i==0 ? 1 : i==1 ? 3 : i==2 ? 6 : 8; }
    HDC D1 (int i) { return i==0 ? 1 : i==1 ? 3 : i==2 ? 3 : 5; }
    HDC D2 (int i) { return i==0 ? 3 : i==1 ? 1 : i==2 ? 5 : 3; }
    HDC XO (int i) { return i==0 ? 0 : i==1 ? 128 : i==2 ? 128 : 512; }
    HDC YO (int i) { return i==0 ? 1 : i==1 ? 0 : i==2 ? 4 : 1; }
    HDC CGO(int i) { return i==0 ? 1 : i==1 ? 35 : i==2 ? 98 : 168; }
};
template<> struct GInfo<2> {   // out l=2 (k=5): paths 2,5,7,10
    static constexpr int NP = 4, K3 = 5, OB = 512;
    HDC PID(int i) { return i==0 ? 2 : i==1 ? 5 : i==2 ? 7 : 10; }
    HDC D1 (int i) { return i==0 ? 1 : i==1 ? 3 : i==2 ? 5 : 5; }
    HDC D2 (int i) { return i==0 ? 5 : i==1 ? 3 : i==2 ? 1 : 5; }
    HDC XO (int i) { return i==0 ? 0 : i==1 ? 128 : i==2 ? 512 : 512; }
    HDC YO (int i) { return i==0 ? 4 : i==1 ? 1 : i==2 ? 0 : 4; }
    HDC CGO(int i) { return i==0 ? 10 : i==1 ? 53 : i==2 ? 143 : 238; }
};

// ---------------- SMEM layout (dynamic) ----------------
// [0, 65536)      : 4 stages x 16KB weight ring (always live, persistent)
// [65536, 75776)  : z buffer (phase 1/2) — reused as phase-3 tree buffer
// [75776, 75840)  : ysh
// [75840, 75872)  : 4 mbarriers
// [75872, 75888)  : 4 per-stage monotonic consume counters
#define NSTAGE 4
#define STAGE_BYTES 16384
#define Z_OFF 65536
#define Y_OFF 75776
#define MB_OFF 75840
#define CNT_OFF 75872
#define SMEM_TOTAL 75904

// ---------------- PTX helpers ----------------

static __device__ __forceinline__ uint32_t smem_u32(const void* p) {
    return (uint32_t)__cvta_generic_to_shared(p);
}

static __device__ __forceinline__ void mbar_init(uint32_t a) {
    asm volatile("mbarrier.init.shared.b64 [%0], 1;" :: "r"(a) : "memory");
}

static __device__ __forceinline__ void mbar_expect(uint32_t a, uint32_t bytes) {
    asm volatile("mbarrier.arrive.expect_tx.shared.b64 _, [%0], %1;"
                 :: "r"(a), "r"(bytes) : "memory");
}

static __device__ __forceinline__ void bulk_cp(uint32_t dst, const void* src, uint32_t mbar) {
    asm volatile("cp.async.bulk.shared::cta.global.mbarrier::complete_tx::bytes [%0], [%1], %2, [%3];"
                 :: "r"(dst), "l"(src), "r"((uint32_t)STAGE_BYTES), "r"(mbar) : "memory");
}

static __device__ __forceinline__ void mbar_wait(uint32_t a, uint32_t parity) {
    asm volatile(
        "{\n\t.reg .pred P;\n"
        "LW_%=:\n\t"
        "mbarrier.try_wait.parity.acquire.cta.shared::cta.b64 P, [%0], %1, 0x989680;\n\t"
        "@P bra LD_%=;\n\t"
        "bra LW_%=;\n"
        "LD_%=:\n\t}"
        :: "r"(a), "r"(parity) : "memory");
}

static __device__ __forceinline__ void fadd2(unsigned long long& a, unsigned long long b) {
    asm("add.rn.f32x2 %0, %0, %1;" : "+l"(a) : "l"(b));
}

// ---------------- Phase-1 body ----------------

template<class GI>
__device__ __forceinline__ void phase1_path(GI, int pl,
                                            const float* __restrict__ x,
                                            const float* __restrict__ ysh,
                                            float* zsh, int n, int u) {
    constexpr int K3 = GI::K3;
    float zv[K3];
    #pragma unroll
    for (int k = 0; k < K3; k++) zv[k] = 0.f;
    const int d1 = GI::D1(pl), d2 = GI::D2(pl);
    const float* xb = x + (size_t)n * XDIM + GI::XO(pl) + u * d1;
    for (int i = 0; i < d1; i++) {
        float xv = xb[i];
        for (int j = 0; j < d2; j++) {
            float xy = xv * ysh[GI::YO(pl) + j];
            const float* cgr = c_cg.v + GI::CGO(pl) + (i * d2 + j) * K3;
            #pragma unroll
            for (int k = 0; k < K3; k++) zv[k] += cgr[k] * xy;
        }
    }
    int base = (pl * 128 + u) * K3;
    #pragma unroll
    for (int k = 0; k < K3; k++) zsh[base + k] = zv[k];
}

// ---------------- Persistent group routine ----------------

template<int G>
__device__ __forceinline__ void run_group(const float* __restrict__ x,
                                          const float* __restrict__ y,
                                          const float* __restrict__ w,
                                          float* __restrict__ out,
                                          char* smem, int bx, int t) {
    using GI = GInfo<G>;
    constexpr int NP = GI::NP, K3 = GI::K3;
    constexpr int NCHUNK = NP * 4;              // 16KB chunks (32 u-rows each)

    const int lane = t & 31, q = t >> 5;
    const uint32_t sb = smem_u32(smem);
    const uint32_t mb = sb + MB_OFF;
    float* zsh = (float*)(smem + Z_OFF);
    float* ysh = (float*)(smem + Y_OFF);
    int* cnt = (int*)(smem + CNT_OFF);
    unsigned long long* tb = (unsigned long long*)(smem + Z_OFF); // tree buffer

    const int snum = (NSAMP - bx + NSM - 1) / NSM;   // samples for this CTA
    const int totalChunks = snum * NCHUNK;

    if (t == 0) {
        #pragma unroll
        for (int s = 0; s < NSTAGE; s++) { mbar_init(mb + 8 * s); cnt[s] = 0; }
    }
    __syncthreads();

    // global chunk g -> source address
    auto chunk_src = [&](int g) -> const char* {
        const int j2 = g / NCHUNK;
        const int c2 = g - j2 * NCHUNK;
        const int n2 = bx + NSM * j2;
        return (const char*)w + (size_t)n2 * (WPER * 4)
               + GI::PID(c2 >> 2) * 65536 + (c2 & 3) * STAGE_BYTES;
    };

    // initial prefetch
    if (t == 0) {
        #pragma unroll
        for (int s = 0; s < NSTAGE; s++) {
            mbar_expect(mb + 8 * s, STAGE_BYTES);
            bulk_cp(sb + s * STAGE_BYTES, chunk_src(s), mb + 8 * s);
        }
    }

    for (int j = 0; j < snum; j++) {
        const int n = bx + NSM * j;

        // ---- Phase 1 (TMA streams in background) ----
        if (t < YDIM) ysh[t] = y[(size_t)n * YDIM + t];
        __syncthreads();   // ysh visible; previous sample's tree reads of zsh done
        if (t < 128) {
            const int u = t;
            #pragma unroll
            for (int pl = 0; pl < NP; pl++)
                phase1_path(GI{}, pl, x, ysh, zsh, n, u);
        }
        __syncthreads();

        // ---- Phase 2: barrier-free chunk pipeline ("last consumer refills") ----
        unsigned long long acc0[K3], acc1[K3];
        #pragma unroll
        for (int k = 0; k < K3; k++) { acc0[k] = 0ull; acc1[k] = 0ull; }

        #pragma unroll
        for (int p = 0; p < NP; p++) {
            #pragma unroll
            for (int r = 0; r < 4; r++) {
                const int cc = j * NCHUNK + p * 4 + r;
                const int s = cc & (NSTAGE - 1);
                mbar_wait(mb + 8 * s, (cc >> 2) & 1);

                // warp q consumes rows q*4 .. q*4+3 of this 32-row chunk
                const char* wrow = smem + s * STAGE_BYTES + (q * 4) * 512 + lane * 16;
                const float* zp = zsh + (p * 128 + r * 32 + q * 4) * K3;
                #pragma unroll
                for (int ui = 0; ui < 4; ui++) {
                    ulonglong2 wv = *reinterpret_cast<const ulonglong2*>(wrow + ui * 512);
                    #pragma unroll
                    for (int k = 0; k < K3; k++) {
                        float zk = zp[ui * K3 + k];
                        unsigned long long zz;
                        asm("mov.b64 %0, {%1, %1};" : "=l"(zz) : "f"(zk));
                        asm("fma.rn.f32x2 %0, %1, %2, %0;" : "+l"(acc0[k]) : "l"(wv.x), "l"(zz));
                        asm("fma.rn.f32x2 %0, %1, %2, %0;" : "+l"(acc1[k]) : "l"(wv.y), "l"(zz));
                    }
                }
                // last consumer of this stage issues the refill immediately
                if (lane == 0) {
                    int old = atomicAdd(&cnt[s], 1);
                    if ((old & 7) == 7) {
                        const int g = cc + NSTAGE;
                        if (g < totalChunks) {
                            mbar_expect(mb + 8 * s, STAGE_BYTES);
                            bulk_cp(sb + s * STAGE_BYTES, chunk_src(g), mb + 8 * s);
                        }
                    }
                }
            }
        }
        __syncthreads();   // all warps done with zsh reads before tree overwrites it

        // ---- Phase 3: cross-warp tree reduction through z buffer ----
        if (q >= 4) {
            int base = ((q - 4) * 32 + lane) * (2 * K3);
            #pragma unroll
            for (int k = 0; k < K3; k++) { tb[base + k] = acc0[k]; tb[base + K3 + k] = acc1[k]; }
        }
        __syncthreads();
        if (q < 4) {
            int base = (q * 32 + lane) * (2 * K3);
            #pragma unroll
            for (int k = 0; k < K3; k++) { fadd2(acc0[k], tb[base + k]); fadd2(acc1[k], tb[base + K3 + k]); }
        }
        __syncthreads();
        if (q >= 2 && q < 4) {
            int base = ((q - 2) * 32 + lane) * (2 * K3);
            #pragma unroll
            for (int k = 0; k < K3; k++) { tb[base + k] = acc0[k]; tb[base + K3 + k] = acc1[k]; }
        }
        __syncthreads();
        if (q < 2) {
            int base = (q * 32 + lane) * (2 * K3);
            #pragma unroll
            for (int k = 0; k < K3; k++) { fadd2(acc0[k], tb[base + k]); fadd2(acc1[k], tb[base + K3 + k]); }
        }
        __syncthreads();
        if (q == 1) {
            int base = lane * (2 * K3);
            #pragma unroll
            for (int k = 0; k < K3; k++) { tb[base + k] = acc0[k]; tb[base + K3 + k] = acc1[k]; }
        }
        __syncthreads();
        if (q == 0) {
            int base = lane * (2 * K3);
            float* outn = out + (size_t)n * XDIM + GI::OB + lane * (4 * K3);
            float res[4 * K3];
            #pragma unroll
            for (int k = 0; k < K3; k++) {
                fadd2(acc0[k], tb[base + k]);
                fadd2(acc1[k], tb[base + K3 + k]);
                float lo, hi;
                asm("mov.b64 {%0,%1}, %2;" : "=f"(lo), "=f"(hi) : "l"(acc0[k]));
                res[0 * K3 + k] = lo;
                res[1 * K3 + k] = hi;
                asm("mov.b64 {%0,%1}, %2;" : "=f"(lo), "=f"(hi) : "l"(acc1[k]));
                res[2 * K3 + k] = lo;
                res[3 * K3 + k] = hi;
            }
            #pragma unroll
            for (int v = 0; v < K3; v++)
                reinterpret_cast<float4*>(outn)[v] =
                    reinterpret_cast<const float4*>(res)[v];
        }
        // loop-top __syncthreads protects zsh/ysh reuse
    }
}

extern __shared__ char dsmem[];

__global__ void __launch_bounds__(256, 3)
tp_kernel(const float* __restrict__ x,
          const float* __restrict__ y,
          const float* __restrict__ w,
          float* __restrict__ out) {
    const int bx = blockIdx.x, g = blockIdx.y, t = threadIdx.x;
    if (g == 0)      run_group<0>(x, y, w, out, dsmem, bx, t);
    else if (g == 1) run_group<1>(x, y, w, out, dsmem, bx, t);
    else             run_group<2>(x, y, w, out, dsmem, bx, t);
}

extern "C" void kernel_launch(void* const* d_in, const int* in_sizes, int n_in,
                              void* d_out, int out_size) {
    const float* x = nullptr;
    const float* y = nullptr;
    const float* w = nullptr;
    for (int i = 0; i < n_in; i++) {
        long sz = in_sizes[i];
        if      (sz == (long)NSAMP * XDIM) x = (const float*)d_in[i];
        else if (sz == (long)NSAMP * YDIM) y = (const float*)d_in[i];
        else if (sz == (long)NSAMP * WPER) w = (const float*)d_in[i];
    }
    if (!x) x = (const float*)d_in[0];
    if (!y) y = (const float*)d_in[1];
    if (!w) w = (const float*)d_in[2];

    cudaFuncSetAttribute(tp_kernel, cudaFuncAttributeMaxDynamicSharedMemorySize, SMEM_TOTAL);
    tp_kernel<<<dim3(NSM, 3), 256, SMEM_TOTAL>>>(x, y, w, (float*)d_out);
}

// round 15
// speedup vs baseline: 1.0908x; 1.0325x over previous
#include <cuda_runtime.h>
#include <cstdint>

#define NPATH 11
#define XDIM 1152
#define YDIM 9
#define WPER 180224
#define NSAMP 1024
#define CGTOT 363
#define NSM 148

// ================= Compile-time CG table (constexpr, fp64) =================

constexpr double cfac(int n) {
    double r = 1.0;
    for (int i = 2; i <= n; ++i) r *= (double)i;
    return r;
}

constexpr double csqrt(double x) {
    if (x <= 0.0) return 0.0;
    double g = x > 1.0 ? x : 1.0;
    for (int it = 0; it < 64; ++it) g = 0.5 * (g + x / g);
    return g;
}

constexpr double su2cg_c(int j1, int m1, int j2, int m2, int j3, int m3) {
    if (m1 + m2 != m3) return 0.0;
    int vmin = -j1 + j2 + m3;
    if (-j1 + m1 > vmin) vmin = -j1 + m1;
    if (vmin < 0) vmin = 0;
    int vmax = j2 + j3 + m1;
    if (j3 - j1 + j2 < vmax) vmax = j3 - j1 + j2;
    if (j3 + m3 < vmax) vmax = j3 + m3;
    double c = csqrt((2.0 * j3 + 1.0) * cfac(j3 + j1 - j2) * cfac(j3 - j1 + j2) * cfac(j1 + j2 - j3)
                     * cfac(j3 + m3) * cfac(j3 - m3)
                     / (cfac(j1 + j2 + j3 + 1) * cfac(j1 - m1) * cfac(j1 + m1)
                        * cfac(j2 - m2) * cfac(j2 + m2)));
    double s = 0.0;
    for (int v = vmin; v <= vmax; ++v) {
        double term = cfac(j2 + j3 + m1 - v) * cfac(j1 - m1 + v)
                      / (cfac(v) * cfac(j3 - j1 + j2 - v) * cfac(j3 + m3 - v) * cfac(v + j1 - j2 - m3));
        s += ((v + j2 + m2) & 1) ? -term : term;
    }
    return c * s;
}

struct QM { double re[25]; double im[25]; };

constexpr QM buildQ_c(int l) {
    QM q{};
    int d = 2 * l + 1;
    const double is2 = 0.70710678118654752440;
    for (int m = -l; m < 0; ++m) {
        q.re[(l + m) * d + (l - m)] = is2;
        q.im[(l + m) * d + (l + m)] = -is2;
    }
    q.re[l * d + l] = 1.0;
    for (int m = 1; m <= l; ++m) {
        double sgn = (m & 1) ? -1.0 : 1.0;
        q.re[(l + m) * d + (l + m)] = sgn * is2;
        q.im[(l + m) * d + (l - m)] = sgn * is2;
    }
    if (l == 1) {
        for (int e = 0; e < d * d; ++e) { double a = q.re[e], b = q.im[e]; q.re[e] = b; q.im[e] = -a; }
    } else if (l == 2) {
        for (int e = 0; e < d * d; ++e) { q.re[e] = -q.re[e]; q.im[e] = -q.im[e]; }
    }
    return q;
}

struct CGTable { float v[CGTOT]; };

constexpr CGTable makeCG() {
    CGTable T{};
    const int L1[NPATH]  = {0,0,0,1,1,1,1,2,2,2,2};
    const int L2c[NPATH] = {0,1,2,0,1,1,2,0,1,2,2};
    const int L3[NPATH]  = {0,1,2,1,0,2,1,2,1,0,2};
    const int CGO[NPATH] = {0,1,10,35,44,53,98,143,168,213,238};
    const double FAN[NPATH] = {384.,512.,512.,512.,384.,512.,512.,512.,512.,384.,512.};
    for (int p = 0; p < NPATH; ++p) {
        int l1 = L1[p], l2 = L2c[p], l3 = L3[p];
        int d1 = 2*l1+1, d2 = 2*l2+1, d3 = 2*l3+1;
        QM Q1 = buildQ_c(l1), Q2 = buildQ_c(l2), Q3 = buildQ_c(l3);
        double C[125] = {};
        for (int i = 0; i < d1; ++i)
            for (int k = 0; k < d2; ++k)
                for (int nn = 0; nn < d3; ++nn)
                    C[(i*d2 + k)*d3 + nn] = su2cg_c(l1, i - l1, l2, k - l2, l3, nn - l3);
        double Cr[125] = {};
        double norm2 = 0.0;
        for (int jj = 0; jj < d1; ++jj)
            for (int ll = 0; ll < d2; ++ll)
                for (int mm = 0; mm < d3; ++mm) {
                    double sr = 0.0;
                    for (int i = 0; i < d1; ++i) {
                        double q1r = Q1.re[i*d1 + jj], q1i = Q1.im[i*d1 + jj];
                        for (int k = 0; k < d2; ++k) {
                            double q2r = Q2.re[k*d2 + ll], q2i = Q2.im[k*d2 + ll];
                            double ar = q1r*q2r - q1i*q2i;
                            double ai = q1r*q2i + q1i*q2r;
                            for (int nn = 0; nn < d3; ++nn) {
                                double c = C[(i*d2 + k)*d3 + nn];
                                sr += c * (ar * Q3.re[nn*d3 + mm] + ai * Q3.im[nn*d3 + mm]);
                            }
                        }
                    }
                    Cr[(jj*d2 + ll)*d3 + mm] = sr;
                    norm2 += sr * sr;
                }
        double scale = csqrt((double)(2*l3 + 1)) / (csqrt(norm2) * csqrt(FAN[p]));
        for (int e = 0; e < d1*d2*d3; ++e)
            T.v[CGO[p] + e] = (float)(Cr[e] * scale);
    }
    return T;
}

__constant__ CGTable c_cg = makeCG();

// ---------------- Group tables ----------------

#define HDC static __host__ __device__ constexpr int

template<int G> struct GInfo;
template<> struct GInfo<0> {   // out l=0 (k=1): paths 0,4,9
    static constexpr int NP = 3, K3 = 1, OB = 0;
    HDC PID(int i) { return i==0 ? 0 : i==1 ? 4 : 9; }
    HDC D1 (int i) { return i==0 ? 1 : i==1 ? 3 : 5; }
    HDC D2 (int i) { return i==0 ? 1 : i==1 ? 3 : 5; }
    HDC XO (int i) { return i==0 ? 0 : i==1 ? 128 : 512; }
    HDC YO (int i) { return i==0 ? 0 : i==1 ? 1 : 4; }
    HDC CGO(int i) { return i==0 ? 0 : i==1 ? 44 : 213; }
};
template<> struct GInfo<1> {   // out l=1 (k=3): paths 1,3,6,8
    static constexpr int NP = 4, K3 = 3, OB = 128;
    HDC PID(int i) { return i==0 ? 1 : i==1 ? 3 : i==2 ? 6 : 8; }
    HDC D1 (int i) { return i==0 ? 1 : i==1 ? 3 : i==2 ? 3 : 5; }
    HDC D2 (int i) { return i==0 ? 3 : i==1 ? 1 : i==2 ? 5 : 3; }
    HDC XO (int i) { return i==0 ? 0 : i==1 ? 128 : i==2 ? 128 : 512; }
    HDC YO (int i) { return i==0 ? 1 : i==1 ? 0 : i==2 ? 4 : 1; }
    HDC CGO(int i) { return i==0 ? 1 : i==1 ? 35 : i==2 ? 98 : 168; }
};
template<> struct GInfo<2> {   // out l=2 (k=5): paths 2,5,7,10
    static constexpr int NP = 4, K3 = 5, OB = 512;
    HDC PID(int i) { return i==0 ? 2 : i==1 ? 5 : i==2 ? 7 : 10; }
    HDC D1 (int i) { return i==0 ? 1 : i==1 ? 3 : i==2 ? 5 : 5; }
    HDC D2 (int i) { return i==0 ? 5 : i==1 ? 3 : i==2 ? 1 : 5; }
    HDC XO (int i) { return i==0 ? 0 : i==1 ? 128 : i==2 ? 512 : 512; }
    HDC YO (int i) { return i==0 ? 4 : i==1 ? 1 : i==2 ? 0 : 4; }
    HDC CGO(int i) { return i==0 ? 10 : i==1 ? 53 : i==2 ? 143 : 238; }
};

// ---------------- SMEM layout (dynamic) ----------------
// [0, 65536)      : 4 stages x 16KB weight ring (always live, persistent)
// [65536, 75776)  : z buffer (phase 1/2) — reused as phase-3 tree buffer
// [75776, 75840)  : ysh
// [75840, 75872)  : 4 mbarriers
// [75872, 75888)  : 4 per-stage monotonic consume counters
#define NSTAGE 4
#define STAGE_BYTES 16384
#define Z_OFF 65536
#define Y_OFF 75776
#define MB_OFF 75840
#define CNT_OFF 75872
#define SMEM_TOTAL 75904

// ---------------- PTX helpers ----------------

static __device__ __forceinline__ uint32_t smem_u32(const void* p) {
    return (uint32_t)__cvta_generic_to_shared(p);
}

static __device__ __forceinline__ void mbar_init(uint32_t a) {
    asm volatile("mbarrier.init.shared.b64 [%0], 1;" :: "r"(a) : "memory");
}

static __device__ __forceinline__ void mbar_expect(uint32_t a, uint32_t bytes) {
    asm volatile("mbarrier.arrive.expect_tx.shared.b64 _, [%0], %1;"
                 :: "r"(a), "r"(bytes) : "memory");
}

static __device__ __forceinline__ uint64_t mk_evict_first_policy() {
    uint64_t pol;
    asm("createpolicy.fractional.L2::evict_first.b64 %0, 1.0;" : "=l"(pol));
    return pol;
}

static __device__ __forceinline__ void bulk_cp(uint32_t dst, const void* src, uint32_t mbar,
                                               uint64_t pol) {
    asm volatile("cp.async.bulk.shared::cta.global.mbarrier::complete_tx::bytes.L2::cache_hint"
                 " [%0], [%1], %2, [%3], %4;"
                 :: "r"(dst), "l"(src), "r"((uint32_t)STAGE_BYTES), "r"(mbar), "l"(pol)
                 : "memory");
}

static __device__ __forceinline__ void mbar_wait(uint32_t a, uint32_t parity) {
    asm volatile(
        "{\n\t.reg .pred P;\n"
        "LW_%=:\n\t"
        "mbarrier.try_wait.parity.acquire.cta.shared::cta.b64 P, [%0], %1, 0x989680;\n\t"
        "@P bra LD_%=;\n\t"
        "bra LW_%=;\n"
        "LD_%=:\n\t}"
        :: "r"(a), "r"(parity) : "memory");
}

static __device__ __forceinline__ void fadd2(unsigned long long& a, unsigned long long b) {
    asm("add.rn.f32x2 %0, %0, %1;" : "+l"(a) : "l"(b));
}

// ---------------- Phase-1 body ----------------

template<class GI>
__device__ __forceinline__ void phase1_path(GI, int pl,
                                            const float* __restrict__ x,
                                            const float* __restrict__ ysh,
                                            float* zsh, int n, int u) {
    constexpr int K3 = GI::K3;
    float zv[K3];
    #pragma unroll
    for (int k = 0; k < K3; k++) zv[k] = 0.f;
    const int d1 = GI::D1(pl), d2 = GI::D2(pl);
    const float* xb = x + (size_t)n * XDIM + GI::XO(pl) + u * d1;
    for (int i = 0; i < d1; i++) {
        float xv = xb[i];
        for (int j = 0; j < d2; j++) {
            float xy = xv * ysh[GI::YO(pl) + j];
            const float* cgr = c_cg.v + GI::CGO(pl) + (i * d2 + j) * K3;
            #pragma unroll
            for (int k = 0; k < K3; k++) zv[k] += cgr[k] * xy;
        }
    }
    int base = (pl * 128 + u) * K3;
    #pragma unroll
    for (int k = 0; k < K3; k++) zsh[base + k] = zv[k];
}

// ---------------- Persistent group routine ----------------

template<int G>
__device__ __forceinline__ void run_group(const float* __restrict__ x,
                                          const float* __restrict__ y,
                                          const float* __restrict__ w,
                                          float* __restrict__ out,
                                          char* smem, int bx, int t) {
    using GI = GInfo<G>;
    constexpr int NP = GI::NP, K3 = GI::K3;
    constexpr int NCHUNK = NP * 4;              // 16KB chunks (32 u-rows each)

    const int lane = t & 31, q = t >> 5;
    const uint32_t sb = smem_u32(smem);
    const uint32_t mb = sb + MB_OFF;
    float* zsh = (float*)(smem + Z_OFF);
    float* ysh = (float*)(smem + Y_OFF);
    int* cnt = (int*)(smem + CNT_OFF);
    unsigned long long* tb = (unsigned long long*)(smem + Z_OFF); // tree buffer

    const uint64_t pol = mk_evict_first_policy();

    const int snum = (NSAMP - bx + NSM - 1) / NSM;   // samples for this CTA
    const int totalChunks = snum * NCHUNK;

    if (t == 0) {
        #pragma unroll
        for (int s = 0; s < NSTAGE; s++) { mbar_init(mb + 8 * s); cnt[s] = 0; }
    }
    __syncthreads();

    // global chunk g -> source address
    auto chunk_src = [&](int g) -> const char* {
        const int j2 = g / NCHUNK;
        const int c2 = g - j2 * NCHUNK;
        const int n2 = bx + NSM * j2;
        return (const char*)w + (size_t)n2 * (WPER * 4)
               + GI::PID(c2 >> 2) * 65536 + (c2 & 3) * STAGE_BYTES;
    };

    // initial prefetch
    if (t == 0) {
        #pragma unroll
        for (int s = 0; s < NSTAGE; s++) {
            mbar_expect(mb + 8 * s, STAGE_BYTES);
            bulk_cp(sb + s * STAGE_BYTES, chunk_src(s), mb + 8 * s, pol);
        }
    }

    for (int j = 0; j < snum; j++) {
        const int n = bx + NSM * j;

        // ---- Phase 1 (TMA streams in background) ----
        if (t < YDIM) ysh[t] = y[(size_t)n * YDIM + t];
        __syncthreads();   // ysh visible; previous sample's tree reads of zsh done
        if (t < 128) {
            const int u = t;
            #pragma unroll
            for (int pl = 0; pl < NP; pl++)
                phase1_path(GI{}, pl, x, ysh, zsh, n, u);
        }
        __syncthreads();

        // ---- Phase 2: barrier-free chunk pipeline ("last consumer refills") ----
        unsigned long long acc0[K3], acc1[K3];
        #pragma unroll
        for (int k = 0; k < K3; k++) { acc0[k] = 0ull; acc1[k] = 0ull; }

        #pragma unroll
        for (int p = 0; p < NP; p++) {
            #pragma unroll
            for (int r = 0; r < 4; r++) {
                const int cc = j * NCHUNK + p * 4 + r;
                const int s = cc & (NSTAGE - 1);
                mbar_wait(mb + 8 * s, (cc >> 2) & 1);

                // warp q consumes rows q*4 .. q*4+3 of this 32-row chunk
                const char* wrow = smem + s * STAGE_BYTES + (q * 4) * 512 + lane * 16;
                const float* zp = zsh + (p * 128 + r * 32 + q * 4) * K3;
                #pragma unroll
                for (int ui = 0; ui < 4; ui++) {
                    ulonglong2 wv = *reinterpret_cast<const ulonglong2*>(wrow + ui * 512);
                    #pragma unroll
                    for (int k = 0; k < K3; k++) {
                        float zk = zp[ui * K3 + k];
                        unsigned long long zz;
                        asm("mov.b64 %0, {%1, %1};" : "=l"(zz) : "f"(zk));
                        asm("fma.rn.f32x2 %0, %1, %2, %0;" : "+l"(acc0[k]) : "l"(wv.x), "l"(zz));
                        asm("fma.rn.f32x2 %0, %1, %2, %0;" : "+l"(acc1[k]) : "l"(wv.y), "l"(zz));
                    }
                }
                // last consumer of this stage issues the refill immediately
                if (lane == 0) {
                    int old = atomicAdd(&cnt[s], 1);
                    if ((old & 7) == 7) {
                        const int g = cc + NSTAGE;
                        if (g < totalChunks) {
                            mbar_expect(mb + 8 * s, STAGE_BYTES);
                            bulk_cp(sb + s * STAGE_BYTES, chunk_src(g), mb + 8 * s, pol);
                        }
                    }
                }
            }
        }
        __syncthreads();   // all warps done with zsh reads before tree overwrites it

        // ---- Phase 3: cross-warp tree reduction through z buffer ----
        if (q >= 4) {
            int base = ((q - 4) * 32 + lane) * (2 * K3);
            #pragma unroll
            for (int k = 0; k < K3; k++) { tb[base + k] = acc0[k]; tb[base + K3 + k] = acc1[k]; }
        }
        __syncthreads();
        if (q < 4) {
            int base = (q * 32 + lane) * (2 * K3);
            #pragma unroll
            for (int k = 0; k < K3; k++) { fadd2(acc0[k], tb[base + k]); fadd2(acc1[k], tb[base + K3 + k]); }
        }
        __syncthreads();
        if (q >= 2 && q < 4) {
            int base = ((q - 2) * 32 + lane) * (2 * K3);
            #pragma unroll
            for (int k = 0; k < K3; k++) { tb[base + k] = acc0[k]; tb[base + K3 + k] = acc1[k]; }
        }
        __syncthreads();
        if (q < 2) {
            int base = (q * 32 + lane) * (2 * K3);
            #pragma unroll
            for (int k = 0; k < K3; k++) { fadd2(acc0[k], tb[base + k]); fadd2(acc1[k], tb[base + K3 + k]); }
        }
        __syncthreads();
        if (q == 1) {
            int base = lane * (2 * K3);
            #pragma unroll
            for (int k = 0; k < K3; k++) { tb[base + k] = acc0[k]; tb[base + K3 + k] = acc1[k]; }
        }
        __syncthreads();
        if (q == 0) {
            int base = lane * (2 * K3);
            float* outn = out + (size_t)n * XDIM + GI::OB + lane * (4 * K3);
            float res[4 * K3];
            #pragma unroll
            for (int k = 0; k < K3; k++) {
                fadd2(acc0[k], tb[base + k]);
                fadd2(acc1[k], tb[base + K3 + k]);
                float lo, hi;
                asm("mov.b64 {%0,%1}, %2;" : "=f"(lo), "=f"(hi) : "l"(acc0[k]));
                res[0 * K3 + k] = lo;
                res[1 * K3 + k] = hi;
                asm("mov.b64 {%0,%1}, %2;" : "=f"(lo), "=f"(hi) : "l"(acc1[k]));
                res[2 * K3 + k] = lo;
                res[3 * K3 + k] = hi;
            }
            #pragma unroll
            for (int v = 0; v < K3; v++)
                reinterpret_cast<float4*>(outn)[v] =
                    reinterpret_cast<const float4*>(res)[v];
        }
        // loop-top __syncthreads protects zsh/ysh reuse
    }
}

extern __shared__ char dsmem[];

__global__ void __launch_bounds__(256, 3)
tp_kernel(const float* __restrict__ x,
          const float* __restrict__ y,
          const float* __restrict__ w,
          float* __restrict__ out) {
    const int bx = blockIdx.x, g = blockIdx.y, t = threadIdx.x;
    if (g == 0)      run_group<0>(x, y, w, out, dsmem, bx, t);
    else if (g == 1) run_group<1>(x, y, w, out, dsmem, bx, t);
    else             run_group<2>(x, y, w, out, dsmem, bx, t);
}

extern "C" void kernel_launch(void* const* d_in, const int* in_sizes, int n_in,
                              void* d_out, int out_size) {
    const float* x = nullptr;
    const float* y = nullptr;
    const float* w = nullptr;
    for (int i = 0; i < n_in; i++) {
        long sz = in_sizes[i];
        if      (sz == (long)NSAMP * XDIM) x = (const float*)d_in[i];
        else if (sz == (long)NSAMP * YDIM) y = (const float*)d_in[i];
        else if (sz == (long)NSAMP * WPER) w = (const float*)d_in[i];
    }
    if (!x) x = (const float*)d_in[0];
    if (!y) y = (const float*)d_in[1];
    if (!w) w = (const float*)d_in[2];

    cudaFuncSetAttribute(tp_kernel, cudaFuncAttributeMaxDynamicSharedMemorySize, SMEM_TOTAL);
    tp_kernel<<<dim3(NSM, 3), 256, SMEM_TOTAL>>>(x, y, w, (float*)d_out);
}